// round 15
// baseline (speedup 1.0000x reference)
#include <cuda_runtime.h>
#include <cuda_fp16.h>
#include <math.h>

// RoIPooling: feat [B,C,50,50] f32, rois [N,5] f32, img scalars -> out [N,C,7,7] f32.
// Bench: B=2, C=256, N=128, IMG=800.
//
// R14 pipeline (best: 17.0us) with g_outT also in FP16 (lossless: max of fp16
// values is fp16-representable; empty-bin 0.0 exact -> output bit-identical).
//  K1 transpose_in : feat[b][c][p] -> featT[b][p][c] (fp16) + bintab fill.
//  K2 roipool_main : block per bin (6272 x 64 thr); thread = 4 channels;
//                    flat offset-table loop; 8B fp16 stores to outT.
//  K3 transpose_out: outT[n][q][c] fp16 -> out[n][c][q] f32; coalesced both sides.

#define C_DIM 256
#define FH 50
#define FW 50
#define NPIX (FH * FW)
#define OH 7
#define OW 7
#define QD (OH * OW)
#define MAX_B 4
#define MAX_ROIS 512
#define MAX_CNT 96

__device__ __align__(16) __half g_featT[MAX_B * NPIX * C_DIM];  // [b][p][c] fp16
__device__ __align__(16) __half g_outT[MAX_ROIS * QD * C_DIM];  // [bin][c] fp16
__device__ int2 g_bintab[MAX_ROIS * QD];                        // {ys|ye|xs|xe, base}

__device__ __forceinline__ float decode_dim(const void* p) {
    int v = *reinterpret_cast<const int*>(p);
    if (v > 0 && v < 1000000) return (float)v;   // int scalar (800 = 0x320)
    return __int_as_float(v);                     // float bits
}

// ---- K1: transpose (f32 -> fp16) + bintab fill ----
__global__ void __launch_bounds__(256)
transpose_in(const float* __restrict__ feat,
             const float* __restrict__ rois,
             const void* __restrict__ img_h_p,
             const void* __restrict__ img_w_p,
             int nbins) {
    __shared__ float s[32][33];
    int b   = blockIdx.z;
    int tp0 = blockIdx.x * 32;
    int tc0 = blockIdx.y * 32;
    int tid = threadIdx.x;

    // ---- side job: first 25 flat-blocks fill the bin-bounds table ----
    {
        int flat = blockIdx.x + gridDim.x * (blockIdx.y + gridDim.y * blockIdx.z);
        int gidx = flat * 256 + tid;
        if (gidx < nbins) {
            int ow = gidx % OW;
            int oh = (gidx / OW) % OH;
            int n  = gidx / QD;

            float img_h = decode_dim(img_h_p);
            float img_w = decode_dim(img_w_p);
            float sh = __fdiv_rn((float)FH, img_h);
            float sw = __fdiv_rn((float)FW, img_w);

            const float* r = rois + n * 5;
            int bidx = (int)r[0];
            // exact reference rounding: single rn-multiply, floor, clamps
            int x1 = max((int)floorf(__fmul_rn(r[1], sw)), 0);
            int y1 = max((int)floorf(__fmul_rn(r[2], sh)), 0);
            int x2 = min((int)floorf(__fmul_rn(r[3], sw)), FW);
            int y2 = min((int)floorf(__fmul_rn(r[4], sh)), FH);

            float bh = __fdiv_rn((float)max(y2 - y1, 1), (float)OH);
            float bw = __fdiv_rn((float)max(x2 - x1, 1), (float)OW);
            float y1f = (float)y1, x1f = (float)x1;
            // mul then add, each correctly rounded (no FMA contraction) — matches jnp
            int ys = (int)floorf(__fadd_rn(y1f, __fmul_rn((float)oh,       bh)));
            int ye = (int)floorf(__fadd_rn(y1f, __fmul_rn((float)(oh + 1), bh)));
            int xs = (int)floorf(__fadd_rn(x1f, __fmul_rn((float)ow,       bw)));
            int xe = (int)floorf(__fadd_rn(x1f, __fmul_rn((float)(ow + 1), bw)));
            ys = min(max(ys, 0), FH - 1);
            ye = min(max(ye, 0), FH);
            xs = min(max(xs, 0), FW - 1);
            xe = min(max(xe, 0), FW);

            g_bintab[gidx] = make_int2(ys | (ye << 8) | (xs << 16) | (xe << 24),
                                       bidx * (NPIX * C_DIM));
        }
    }

    // ---- transpose tile ----
    {
        int cl = tid >> 3;
        int p0 = tp0 + ((tid & 7) << 2);
        if (p0 < NPIX) {             // NPIX%4==0, p0%4==0 -> p0+3 < NPIX
            float4 v = *reinterpret_cast<const float4*>(
                feat + ((size_t)(b * C_DIM + tc0 + cl)) * NPIX + p0);
            int pl = (tid & 7) << 2;
            s[cl][pl + 0] = v.x;
            s[cl][pl + 1] = v.y;
            s[cl][pl + 2] = v.z;
            s[cl][pl + 3] = v.w;
        }
    }
    __syncthreads();
    {
        int pl = tid >> 3;
        int p  = tp0 + pl;
        if (p < NPIX) {
            int c0 = (tid & 7) << 2;
            __half2 h0 = __floats2half2_rn(s[c0 + 0][pl], s[c0 + 1][pl]);
            __half2 h1 = __floats2half2_rn(s[c0 + 2][pl], s[c0 + 3][pl]);
            uint2 v;
            v.x = *reinterpret_cast<unsigned*>(&h0);
            v.y = *reinterpret_cast<unsigned*>(&h1);
            *reinterpret_cast<uint2*>(
                g_featT + ((size_t)b * NPIX + p) * C_DIM + tc0 + c0) = v;
        }
    }
}

// ---- K2: block per bin; 64 threads; thread = 4 channels (2x half2) ----
__global__ void __launch_bounds__(64)
roipool_main() {
    int bin = blockIdx.x;
    int t   = threadIdx.x;           // 0..63

    __shared__ int s_offs[MAX_CNT];

    int2 e = g_bintab[bin];          // 8B broadcast load
    int pb = e.x;
    int ys =  pb        & 0xFF;
    int ye = (pb >> 8)  & 0xFF;
    int xs = (pb >> 16) & 0xFF;
    int xe = (pb >> 24) & 0xFF;

    int rows = ye - ys;
    int cols = xe - xs;
    int count = (rows > 0 && cols > 0) ? rows * cols : 0;

    if (t < count) {
        int yy = ys + t / cols;
        int xx = xs + t % cols;
        s_offs[t] = (yy * FW + xx) * C_DIM;   // element (half) offsets
    }
    __syncthreads();

    const __half* base = g_featT + e.y + (t << 2);

    __half2 ninf = __float2half2_rn(-INFINITY);
    __half2 m0 = ninf, m1 = ninf;
    int i = 0;
    for (; i + 4 <= count; i += 4) {
        uint2 v0 = *reinterpret_cast<const uint2*>(base + s_offs[i + 0]);
        uint2 v1 = *reinterpret_cast<const uint2*>(base + s_offs[i + 1]);
        uint2 v2 = *reinterpret_cast<const uint2*>(base + s_offs[i + 2]);
        uint2 v3 = *reinterpret_cast<const uint2*>(base + s_offs[i + 3]);
        __half2 a0 = *reinterpret_cast<__half2*>(&v0.x);
        __half2 b0 = *reinterpret_cast<__half2*>(&v0.y);
        __half2 a1 = *reinterpret_cast<__half2*>(&v1.x);
        __half2 b1 = *reinterpret_cast<__half2*>(&v1.y);
        __half2 a2 = *reinterpret_cast<__half2*>(&v2.x);
        __half2 b2 = *reinterpret_cast<__half2*>(&v2.y);
        __half2 a3 = *reinterpret_cast<__half2*>(&v3.x);
        __half2 b3 = *reinterpret_cast<__half2*>(&v3.y);
        m0 = __hmax2(m0, __hmax2(__hmax2(a0, a1), __hmax2(a2, a3)));
        m1 = __hmax2(m1, __hmax2(__hmax2(b0, b1), __hmax2(b2, b3)));
    }
    for (; i < count; ++i) {
        uint2 v = *reinterpret_cast<const uint2*>(base + s_offs[i]);
        m0 = __hmax2(m0, *reinterpret_cast<__half2*>(&v.x));
        m1 = __hmax2(m1, *reinterpret_cast<__half2*>(&v.y));
    }

    if (count == 0) {
        m0 = __float2half2_rn(0.0f);
        m1 = __float2half2_rn(0.0f);
    }
    uint2 o;
    o.x = *reinterpret_cast<unsigned*>(&m0);
    o.y = *reinterpret_cast<unsigned*>(&m1);
    *reinterpret_cast<uint2*>(g_outT + (size_t)bin * C_DIM + (t << 2)) = o;
}

// ---- K3: g_outT [n][q][c] fp16 -> out [n][c][q] f32; block per (n, c-half) ----
__global__ void __launch_bounds__(256)
transpose_out(float* __restrict__ out) {
    __shared__ __align__(16) float s[128 * QD];   // [c_local][q] f32, stride 49
    int n = blockIdx.x;
    int h = blockIdx.y;
    int tid = threadIdx.x;

    const __half* src = g_outT + (size_t)n * (QD * C_DIM) + h * 128;
    // each thread: one half2 = 2 channels of one q; 64 half2 per q-row (coalesced)
    for (int idx = tid; idx < QD * 64; idx += 256) {
        int q  = idx >> 6;           // idx / 64
        int cp = idx & 63;           // half2 index within the 128-channel half
        __half2 v = *reinterpret_cast<const __half2*>(src + (size_t)q * C_DIM + cp * 2);
        float2 f = __half22float2(v);
        s[(cp * 2 + 0) * QD + q] = f.x;
        s[(cp * 2 + 1) * QD + q] = f.y;
    }
    __syncthreads();

    float4* dst = reinterpret_cast<float4*>(
        out + (size_t)n * (C_DIM * QD) + (size_t)h * 128 * QD);
    const float4* ss = reinterpret_cast<const float4*>(s);
    for (int idx = tid; idx < (128 * QD) / 4; idx += 256) {
        dst[idx] = ss[idx];
    }
}

extern "C" void kernel_launch(void* const* d_in, const int* in_sizes, int n_in,
                              void* d_out, int out_size) {
    const float* feat = (const float*)d_in[0];
    const float* rois = (const float*)d_in[1];
    const void*  imh  = d_in[2];
    const void*  imw  = d_in[3];
    float* out = (float*)d_out;

    int B = in_sizes[0] / (C_DIM * NPIX);
    int nrois = in_sizes[1] / 5;
    int nbins = nrois * QD;

    dim3 tg((NPIX + 31) / 32, C_DIM / 32, B);
    transpose_in<<<tg, 256>>>(feat, rois, imh, imw, nbins);

    roipool_main<<<nbins, 64>>>();

    dim3 og(nrois, 2);
    transpose_out<<<og, 256>>>(out);
}

// round 16
// speedup vs baseline: 1.0050x; 1.0050x over previous
#include <cuda_runtime.h>
#include <cuda_fp16.h>
#include <math.h>

// RoIPooling: feat [B,C,50,50] f32, rois [N,5] f32, img scalars -> out [N,C,7,7] f32.
// Bench: B=2, C=256, N=128, IMG=800.
//
// R14 pipeline — best measured (17.0us), reverted verbatim after R15's fp16-outT
// variant regressed (noise-dominated regime; locking in the verified best):
//  K1 transpose_in : feat[b][c][p] -> featT[b][p][c] (fp16) + bintab fill.
//  K2 roipool_main : block per bin (6272 x 64 thr); thread = 4 channels (half2x2);
//                    block-uniform smem offset table; flat unrolled loop; f32 outT.
//  K3 transpose_out: g_outT[n][q][c] (f32) -> out[n][c][q]; coalesced, float4 drain.

#define C_DIM 256
#define FH 50
#define FW 50
#define NPIX (FH * FW)
#define OH 7
#define OW 7
#define QD (OH * OW)
#define MAX_B 4
#define MAX_ROIS 512
#define MAX_CNT 96

__device__ __align__(16) __half g_featT[MAX_B * NPIX * C_DIM];  // [b][p][c] fp16
__device__ __align__(16) float g_outT[MAX_ROIS * QD * C_DIM];   // [bin][c] f32
__device__ int2 g_bintab[MAX_ROIS * QD];                        // {ys|ye|xs|xe, base}

__device__ __forceinline__ float decode_dim(const void* p) {
    int v = *reinterpret_cast<const int*>(p);
    if (v > 0 && v < 1000000) return (float)v;   // int scalar (800 = 0x320)
    return __int_as_float(v);                     // float bits
}

// ---- K1: transpose (f32 -> fp16) + bintab fill ----
__global__ void __launch_bounds__(256)
transpose_in(const float* __restrict__ feat,
             const float* __restrict__ rois,
             const void* __restrict__ img_h_p,
             const void* __restrict__ img_w_p,
             int nbins) {
    __shared__ float s[32][33];
    int b   = blockIdx.z;
    int tp0 = blockIdx.x * 32;
    int tc0 = blockIdx.y * 32;
    int tid = threadIdx.x;

    // ---- side job: first 25 flat-blocks fill the bin-bounds table ----
    {
        int flat = blockIdx.x + gridDim.x * (blockIdx.y + gridDim.y * blockIdx.z);
        int gidx = flat * 256 + tid;
        if (gidx < nbins) {
            int ow = gidx % OW;
            int oh = (gidx / OW) % OH;
            int n  = gidx / QD;

            float img_h = decode_dim(img_h_p);
            float img_w = decode_dim(img_w_p);
            float sh = __fdiv_rn((float)FH, img_h);
            float sw = __fdiv_rn((float)FW, img_w);

            const float* r = rois + n * 5;
            int bidx = (int)r[0];
            // exact reference rounding: single rn-multiply, floor, clamps
            int x1 = max((int)floorf(__fmul_rn(r[1], sw)), 0);
            int y1 = max((int)floorf(__fmul_rn(r[2], sh)), 0);
            int x2 = min((int)floorf(__fmul_rn(r[3], sw)), FW);
            int y2 = min((int)floorf(__fmul_rn(r[4], sh)), FH);

            float bh = __fdiv_rn((float)max(y2 - y1, 1), (float)OH);
            float bw = __fdiv_rn((float)max(x2 - x1, 1), (float)OW);
            float y1f = (float)y1, x1f = (float)x1;
            // mul then add, each correctly rounded (no FMA contraction) — matches jnp
            int ys = (int)floorf(__fadd_rn(y1f, __fmul_rn((float)oh,       bh)));
            int ye = (int)floorf(__fadd_rn(y1f, __fmul_rn((float)(oh + 1), bh)));
            int xs = (int)floorf(__fadd_rn(x1f, __fmul_rn((float)ow,       bw)));
            int xe = (int)floorf(__fadd_rn(x1f, __fmul_rn((float)(ow + 1), bw)));
            ys = min(max(ys, 0), FH - 1);
            ye = min(max(ye, 0), FH);
            xs = min(max(xs, 0), FW - 1);
            xe = min(max(xe, 0), FW);

            g_bintab[gidx] = make_int2(ys | (ye << 8) | (xs << 16) | (xe << 24),
                                       bidx * (NPIX * C_DIM));
        }
    }

    // ---- transpose tile ----
    {
        int cl = tid >> 3;
        int p0 = tp0 + ((tid & 7) << 2);
        if (p0 < NPIX) {             // NPIX%4==0, p0%4==0 -> p0+3 < NPIX
            float4 v = *reinterpret_cast<const float4*>(
                feat + ((size_t)(b * C_DIM + tc0 + cl)) * NPIX + p0);
            int pl = (tid & 7) << 2;
            s[cl][pl + 0] = v.x;
            s[cl][pl + 1] = v.y;
            s[cl][pl + 2] = v.z;
            s[cl][pl + 3] = v.w;
        }
    }
    __syncthreads();
    {
        int pl = tid >> 3;
        int p  = tp0 + pl;
        if (p < NPIX) {
            int c0 = (tid & 7) << 2;
            __half2 h0 = __floats2half2_rn(s[c0 + 0][pl], s[c0 + 1][pl]);
            __half2 h1 = __floats2half2_rn(s[c0 + 2][pl], s[c0 + 3][pl]);
            uint2 v;
            v.x = *reinterpret_cast<unsigned*>(&h0);
            v.y = *reinterpret_cast<unsigned*>(&h1);
            *reinterpret_cast<uint2*>(
                g_featT + ((size_t)b * NPIX + p) * C_DIM + tc0 + c0) = v;
        }
    }
}

// ---- K2: block per bin; 64 threads; thread = 4 channels (2x half2) ----
__global__ void __launch_bounds__(64)
roipool_main() {
    int bin = blockIdx.x;
    int t   = threadIdx.x;           // 0..63

    __shared__ int s_offs[MAX_CNT];

    int2 e = g_bintab[bin];          // 8B broadcast load
    int pb = e.x;
    int ys =  pb        & 0xFF;
    int ye = (pb >> 8)  & 0xFF;
    int xs = (pb >> 16) & 0xFF;
    int xe = (pb >> 24) & 0xFF;

    int rows = ye - ys;
    int cols = xe - xs;
    int count = (rows > 0 && cols > 0) ? rows * cols : 0;

    if (t < count) {
        int yy = ys + t / cols;
        int xx = xs + t % cols;
        s_offs[t] = (yy * FW + xx) * C_DIM;   // element (half) offsets
    }
    __syncthreads();

    const __half* base = g_featT + e.y + (t << 2);

    __half2 ninf = __float2half2_rn(-INFINITY);
    __half2 m0 = ninf, m1 = ninf;
    int i = 0;
    for (; i + 4 <= count; i += 4) {
        uint2 v0 = *reinterpret_cast<const uint2*>(base + s_offs[i + 0]);
        uint2 v1 = *reinterpret_cast<const uint2*>(base + s_offs[i + 1]);
        uint2 v2 = *reinterpret_cast<const uint2*>(base + s_offs[i + 2]);
        uint2 v3 = *reinterpret_cast<const uint2*>(base + s_offs[i + 3]);
        __half2 a0 = *reinterpret_cast<__half2*>(&v0.x);
        __half2 b0 = *reinterpret_cast<__half2*>(&v0.y);
        __half2 a1 = *reinterpret_cast<__half2*>(&v1.x);
        __half2 b1 = *reinterpret_cast<__half2*>(&v1.y);
        __half2 a2 = *reinterpret_cast<__half2*>(&v2.x);
        __half2 b2 = *reinterpret_cast<__half2*>(&v2.y);
        __half2 a3 = *reinterpret_cast<__half2*>(&v3.x);
        __half2 b3 = *reinterpret_cast<__half2*>(&v3.y);
        m0 = __hmax2(m0, __hmax2(__hmax2(a0, a1), __hmax2(a2, a3)));
        m1 = __hmax2(m1, __hmax2(__hmax2(b0, b1), __hmax2(b2, b3)));
    }
    for (; i < count; ++i) {
        uint2 v = *reinterpret_cast<const uint2*>(base + s_offs[i]);
        m0 = __hmax2(m0, *reinterpret_cast<__half2*>(&v.x));
        m1 = __hmax2(m1, *reinterpret_cast<__half2*>(&v.y));
    }

    float4 o;
    float2 f0 = __half22float2(m0);
    float2 f1 = __half22float2(m1);
    o.x = f0.x; o.y = f0.y; o.z = f1.x; o.w = f1.y;
    if (count == 0) o = make_float4(0.f, 0.f, 0.f, 0.f);

    *reinterpret_cast<float4*>(g_outT + (size_t)bin * C_DIM + (t << 2)) = o;
}

// ---- K3: g_outT [n][q][c] -> out [n][c][q]; block per (n, channel-half) ----
__global__ void __launch_bounds__(256)
transpose_out(float* __restrict__ out) {
    __shared__ __align__(16) float s[128 * QD];   // stride 49: conflict-free
    int n = blockIdx.x;
    int h = blockIdx.y;
    int tid = threadIdx.x;

    const float* src = g_outT + (size_t)n * (QD * C_DIM) + h * 128;
    for (int idx = tid; idx < QD * 128; idx += 256) {
        int q  = idx >> 7;
        int cl = idx & 127;
        s[cl * QD + q] = src[(size_t)q * C_DIM + cl];   // gmem coalesced
    }
    __syncthreads();

    float4* dst = reinterpret_cast<float4*>(
        out + (size_t)n * (C_DIM * QD) + (size_t)h * 128 * QD);
    const float4* ss = reinterpret_cast<const float4*>(s);
    for (int idx = tid; idx < (128 * QD) / 4; idx += 256) {
        dst[idx] = ss[idx];
    }
}

extern "C" void kernel_launch(void* const* d_in, const int* in_sizes, int n_in,
                              void* d_out, int out_size) {
    const float* feat = (const float*)d_in[0];
    const float* rois = (const float*)d_in[1];
    const void*  imh  = d_in[2];
    const void*  imw  = d_in[3];
    float* out = (float*)d_out;

    int B = in_sizes[0] / (C_DIM * NPIX);
    int nrois = in_sizes[1] / 5;
    int nbins = nrois * QD;

    dim3 tg((NPIX + 31) / 32, C_DIM / 32, B);
    transpose_in<<<tg, 256>>>(feat, rois, imh, imw, nbins);

    roipool_main<<<nbins, 64>>>();

    dim3 og(nrois, 2);
    transpose_out<<<og, 256>>>(out);
}

// round 17
// speedup vs baseline: 1.0152x; 1.0102x over previous
#include <cuda_runtime.h>
#include <cuda_fp16.h>
#include <math.h>

// RoIPooling: feat [B,C,50,50] f32, rois [N,5] f32, img scalars -> out [N,C,7,7] f32.
// Bench: B=2, C=256, N=128, IMG=800.
//
//  K1 transpose_in : feat[b][c][p] -> featT[b][p][c] (fp16) + bintab fill (as R14).
//  K2 roipool_main : WARP per bin (784 blocks x 256 thr); lane = 8 channels (uint4
//                    fp16 = one 512B warp-request per pixel); pixel offsets in 2
//                    registers, broadcast via shfl (no smem, no block sync).
//  K3 transpose_out: g_outT[n][q][c] f32 -> out[n][c][q] (as R14).

#define C_DIM 256
#define FH 50
#define FW 50
#define NPIX (FH * FW)
#define OH 7
#define OW 7
#define QD (OH * OW)
#define MAX_B 4
#define MAX_ROIS 512

__device__ __align__(16) __half g_featT[MAX_B * NPIX * C_DIM];  // [b][p][c] fp16
__device__ __align__(16) float g_outT[MAX_ROIS * QD * C_DIM];   // [bin][c] f32
__device__ int2 g_bintab[MAX_ROIS * QD];                        // {ys|ye|xs|xe, base}

__device__ __forceinline__ float decode_dim(const void* p) {
    int v = *reinterpret_cast<const int*>(p);
    if (v > 0 && v < 1000000) return (float)v;   // int scalar (800 = 0x320)
    return __int_as_float(v);                     // float bits
}

// ---- K1: transpose (f32 -> fp16) + bintab fill (byte-identical to R14) ----
__global__ void __launch_bounds__(256)
transpose_in(const float* __restrict__ feat,
             const float* __restrict__ rois,
             const void* __restrict__ img_h_p,
             const void* __restrict__ img_w_p,
             int nbins) {
    __shared__ float s[32][33];
    int b   = blockIdx.z;
    int tp0 = blockIdx.x * 32;
    int tc0 = blockIdx.y * 32;
    int tid = threadIdx.x;

    // ---- side job: first 25 flat-blocks fill the bin-bounds table ----
    {
        int flat = blockIdx.x + gridDim.x * (blockIdx.y + gridDim.y * blockIdx.z);
        int gidx = flat * 256 + tid;
        if (gidx < nbins) {
            int ow = gidx % OW;
            int oh = (gidx / OW) % OH;
            int n  = gidx / QD;

            float img_h = decode_dim(img_h_p);
            float img_w = decode_dim(img_w_p);
            float sh = __fdiv_rn((float)FH, img_h);
            float sw = __fdiv_rn((float)FW, img_w);

            const float* r = rois + n * 5;
            int bidx = (int)r[0];
            // exact reference rounding: single rn-multiply, floor, clamps
            int x1 = max((int)floorf(__fmul_rn(r[1], sw)), 0);
            int y1 = max((int)floorf(__fmul_rn(r[2], sh)), 0);
            int x2 = min((int)floorf(__fmul_rn(r[3], sw)), FW);
            int y2 = min((int)floorf(__fmul_rn(r[4], sh)), FH);

            float bh = __fdiv_rn((float)max(y2 - y1, 1), (float)OH);
            float bw = __fdiv_rn((float)max(x2 - x1, 1), (float)OW);
            float y1f = (float)y1, x1f = (float)x1;
            // mul then add, each correctly rounded (no FMA contraction) — matches jnp
            int ys = (int)floorf(__fadd_rn(y1f, __fmul_rn((float)oh,       bh)));
            int ye = (int)floorf(__fadd_rn(y1f, __fmul_rn((float)(oh + 1), bh)));
            int xs = (int)floorf(__fadd_rn(x1f, __fmul_rn((float)ow,       bw)));
            int xe = (int)floorf(__fadd_rn(x1f, __fmul_rn((float)(ow + 1), bw)));
            ys = min(max(ys, 0), FH - 1);
            ye = min(max(ye, 0), FH);
            xs = min(max(xs, 0), FW - 1);
            xe = min(max(xe, 0), FW);

            g_bintab[gidx] = make_int2(ys | (ye << 8) | (xs << 16) | (xe << 24),
                                       bidx * (NPIX * C_DIM));
        }
    }

    // ---- transpose tile ----
    {
        int cl = tid >> 3;
        int p0 = tp0 + ((tid & 7) << 2);
        if (p0 < NPIX) {             // NPIX%4==0, p0%4==0 -> p0+3 < NPIX
            float4 v = *reinterpret_cast<const float4*>(
                feat + ((size_t)(b * C_DIM + tc0 + cl)) * NPIX + p0);
            int pl = (tid & 7) << 2;
            s[cl][pl + 0] = v.x;
            s[cl][pl + 1] = v.y;
            s[cl][pl + 2] = v.z;
            s[cl][pl + 3] = v.w;
        }
    }
    __syncthreads();
    {
        int pl = tid >> 3;
        int p  = tp0 + pl;
        if (p < NPIX) {
            int c0 = (tid & 7) << 2;
            __half2 h0 = __floats2half2_rn(s[c0 + 0][pl], s[c0 + 1][pl]);
            __half2 h1 = __floats2half2_rn(s[c0 + 2][pl], s[c0 + 3][pl]);
            uint2 v;
            v.x = *reinterpret_cast<unsigned*>(&h0);
            v.y = *reinterpret_cast<unsigned*>(&h1);
            *reinterpret_cast<uint2*>(
                g_featT + ((size_t)b * NPIX + p) * C_DIM + tc0 + c0) = v;
        }
    }
}

// ---- K2: WARP per bin; lane = 8 channels (uint4 fp16); shfl-broadcast offsets ----
__global__ void __launch_bounds__(256)
roipool_main() {
    int w    = threadIdx.x >> 5;     // warp 0..7
    int lane = threadIdx.x & 31;
    int bin  = blockIdx.x * 8 + w;

    int2 e = g_bintab[bin];          // one 8B broadcast load per warp
    int pb = e.x;
    int ys =  pb        & 0xFF;
    int ye = (pb >> 8)  & 0xFF;
    int xs = (pb >> 16) & 0xFF;
    int xe = (pb >> 24) & 0xFF;

    int rows = ye - ys;
    int cols = xe - xs;
    int cnt = (rows > 0 && cols > 0) ? rows * cols : 0;   // <= 64

    // pixel offsets in registers: lane holds pixels (lane) and (lane+32)
    int o0 = 0, o1 = 0;
    if (lane < cnt) {
        int yy = ys + lane / cols;
        int xx = xs + lane % cols;
        o0 = (yy * FW + xx) * C_DIM;
    }
    if (lane + 32 < cnt) {
        int l2 = lane + 32;
        int yy = ys + l2 / cols;
        int xx = xs + l2 % cols;
        o1 = (yy * FW + xx) * C_DIM;
    }

    const __half* base = g_featT + e.y + (lane << 3);   // 8 halves = 16B per lane

    __half2 ninf = __float2half2_rn(-INFINITY);
    __half2 m0 = ninf, m1 = ninf, m2 = ninf, m3 = ninf;

    int n1 = cnt < 32 ? cnt : 32;
    for (int i = 0; i < n1; ++i) {
        int off = __shfl_sync(0xffffffffu, o0, i);
        uint4 v = *reinterpret_cast<const uint4*>(base + off);
        m0 = __hmax2(m0, *reinterpret_cast<__half2*>(&v.x));
        m1 = __hmax2(m1, *reinterpret_cast<__half2*>(&v.y));
        m2 = __hmax2(m2, *reinterpret_cast<__half2*>(&v.z));
        m3 = __hmax2(m3, *reinterpret_cast<__half2*>(&v.w));
    }
    for (int i = 32; i < cnt; ++i) {
        int off = __shfl_sync(0xffffffffu, o1, i - 32);
        uint4 v = *reinterpret_cast<const uint4*>(base + off);
        m0 = __hmax2(m0, *reinterpret_cast<__half2*>(&v.x));
        m1 = __hmax2(m1, *reinterpret_cast<__half2*>(&v.y));
        m2 = __hmax2(m2, *reinterpret_cast<__half2*>(&v.z));
        m3 = __hmax2(m3, *reinterpret_cast<__half2*>(&v.w));
    }

    float2 f0 = __half22float2(m0);
    float2 f1 = __half22float2(m1);
    float2 f2 = __half22float2(m2);
    float2 f3 = __half22float2(m3);
    float4 a = make_float4(f0.x, f0.y, f1.x, f1.y);
    float4 b = make_float4(f2.x, f2.y, f3.x, f3.y);
    if (cnt == 0) {
        a = make_float4(0.f, 0.f, 0.f, 0.f);
        b = a;
    }

    float* dst = g_outT + (size_t)bin * C_DIM + (lane << 3);
    *reinterpret_cast<float4*>(dst)     = a;
    *reinterpret_cast<float4*>(dst + 4) = b;
}

// ---- K3: g_outT [n][q][c] -> out [n][c][q] (byte-identical to R14) ----
__global__ void __launch_bounds__(256)
transpose_out(float* __restrict__ out) {
    __shared__ __align__(16) float s[128 * QD];   // stride 49: conflict-free
    int n = blockIdx.x;
    int h = blockIdx.y;
    int tid = threadIdx.x;

    const float* src = g_outT + (size_t)n * (QD * C_DIM) + h * 128;
    for (int idx = tid; idx < QD * 128; idx += 256) {
        int q  = idx >> 7;
        int cl = idx & 127;
        s[cl * QD + q] = src[(size_t)q * C_DIM + cl];   // gmem coalesced
    }
    __syncthreads();

    float4* dst = reinterpret_cast<float4*>(
        out + (size_t)n * (C_DIM * QD) + (size_t)h * 128 * QD);
    const float4* ss = reinterpret_cast<const float4*>(s);
    for (int idx = tid; idx < (128 * QD) / 4; idx += 256) {
        dst[idx] = ss[idx];
    }
}

extern "C" void kernel_launch(void* const* d_in, const int* in_sizes, int n_in,
                              void* d_out, int out_size) {
    const float* feat = (const float*)d_in[0];
    const float* rois = (const float*)d_in[1];
    const void*  imh  = d_in[2];
    const void*  imw  = d_in[3];
    float* out = (float*)d_out;

    int B = in_sizes[0] / (C_DIM * NPIX);
    int nrois = in_sizes[1] / 5;
    int nbins = nrois * QD;

    dim3 tg((NPIX + 31) / 32, C_DIM / 32, B);
    transpose_in<<<tg, 256>>>(feat, rois, imh, imw, nbins);

    roipool_main<<<nbins / 8, 256>>>();

    dim3 og(nrois, 2);
    transpose_out<<<og, 256>>>(out);
}